// round 7
// baseline (speedup 1.0000x reference)
#include <cuda_runtime.h>
#include <cuda_bf16.h>

#define NN 100000
#define EE 600000
#define HD 128
#define OD3 64
#define AST 272          // A row stride bytes (136 bf16): 128 cols + 8 pad
#define BSB 144          // B row stride bytes (72 bf16): 64 cols + 8 pad
#define BSE 72

typedef unsigned long long u64;
typedef unsigned int u32;

// ---------------- scratch (device globals) ----------------
__device__ float g_hA[(size_t)NN * HD];   // layer-1 output
__device__ float g_hB[(size_t)NN * HD];   // layer-2 output (ping-pong: no in-place)
__device__ int   g_cnt[NN];               // zero at rest; re-zeroed by k_scan each call
__device__ int   g_rowstart[NN + 1];
__device__ int   g_cursor[NN];
__device__ int   g_csrc[EE];
// padded bf16 weight images per 64-wide K chunk: [chunk 0..3][split hi/lo][n*BSE + kk]
// chunks 0,1 = Wl k[0:64),[64:128); chunks 2,3 = Wr. B = W^T.
__device__ __align__(16) __nv_bfloat16 g_bimg[4][2][HD * BSE];

// ---------------- PTX helpers ----------------
__device__ __forceinline__ u32 smem_u32(const void* p) {
    u32 a;
    asm("{ .reg .u64 t; cvta.to.shared.u64 t, %1; cvt.u32.u64 %0, t; }" : "=r"(a) : "l"(p));
    return a;
}
__device__ __forceinline__ void ldsm4(u32* r, u32 addr) {
    asm volatile("ldmatrix.sync.aligned.m8n8.x4.shared.b16 {%0,%1,%2,%3}, [%4];"
                 : "=r"(r[0]), "=r"(r[1]), "=r"(r[2]), "=r"(r[3]) : "r"(addr));
}
__device__ __forceinline__ void ldsm2(u32* r, u32 addr) {
    asm volatile("ldmatrix.sync.aligned.m8n8.x2.shared.b16 {%0,%1}, [%2];"
                 : "=r"(r[0]), "=r"(r[1]) : "r"(addr));
}
__device__ __forceinline__ void mma16816(float* c, const u32* a, const u32* b) {
    asm volatile("mma.sync.aligned.m16n8k16.row.col.f32.bf16.bf16.f32 "
                 "{%0,%1,%2,%3}, {%4,%5,%6,%7}, {%8,%9}, {%0,%1,%2,%3};"
                 : "+f"(c[0]), "+f"(c[1]), "+f"(c[2]), "+f"(c[3])
                 : "r"(a[0]), "r"(a[1]), "r"(a[2]), "r"(a[3]), "r"(b[0]), "r"(b[1]));
}
// split a float4 into hi/lo bf16x2-pair u64s
__device__ __forceinline__ void split4(float4 v, u64& hi, u64& lo) {
    __nv_bfloat162 h0 = __floats2bfloat162_rn(v.x, v.y);
    __nv_bfloat162 h1 = __floats2bfloat162_rn(v.z, v.w);
    float2 f0 = __bfloat1622float2(h0);
    float2 f1 = __bfloat1622float2(h1);
    __nv_bfloat162 l0 = __floats2bfloat162_rn(v.x - f0.x, v.y - f0.y);
    __nv_bfloat162 l1 = __floats2bfloat162_rn(v.z - f1.x, v.w - f1.y);
    hi = (u64)(*(u32*)&h0) | ((u64)(*(u32*)&h1) << 32);
    lo = (u64)(*(u32*)&l0) | ((u64)(*(u32*)&l1) << 32);
}

// ================= CSR build =================
__global__ void k_hist(const int* __restrict__ dst) {
    int e = blockIdx.x * blockDim.x + threadIdx.x;
    if (e < EE) atomicAdd(&g_cnt[dst[e]], 1);
}

__global__ void k_scan() {   // single block, 1024 threads
    __shared__ int sh[1024];
    const int tid = threadIdx.x;
    const int CH = (NN + 1023) / 1024;
    int base = tid * CH;
    int end  = min(base + CH, NN);
    int s = 0;
    #pragma unroll 4
    for (int i = base; i < end; i++) s += g_cnt[i];
    sh[tid] = s;
    __syncthreads();
    for (int off = 1; off < 1024; off <<= 1) {
        int v = (tid >= off) ? sh[tid - off] : 0;
        __syncthreads();
        sh[tid] += v;
        __syncthreads();
    }
    int run = sh[tid] - s;
    for (int i = base; i < end; i++) {
        int c = g_cnt[i];
        g_rowstart[i] = run;
        g_cursor[i]   = run;
        g_cnt[i]      = 0;      // restore invariant for next replay
        run += c;
    }
    if (tid == 0) g_rowstart[NN] = EE;
}

__global__ void k_slot(const int* __restrict__ src, const int* __restrict__ dst) {
    int e = blockIdx.x * blockDim.x + threadIdx.x;
    if (e < EE) {
        int d = dst[e];
        int slot = atomicAdd(&g_cursor[d], 1);
        g_csrc[slot] = src[e];
    }
}

// ================= weight prepack: 4 K-chunks, B = W^T, bf16 hi/lo =================
template<int N_>
__global__ void k_bpack(const float* __restrict__ Wl, const float* __restrict__ Wr) {
    int t = blockIdx.x * blockDim.x + threadIdx.x;
    if (t >= 4 * 64 * N_) return;
    int chunk = t / (64 * N_);
    int rem = t - chunk * 64 * N_;
    int kk = rem / N_, n = rem % N_;
    const float* W = (chunk < 2) ? Wl : Wr;
    int gk = (chunk & 1) * 64 + kk;
    float v = __ldg(W + gk * N_ + n);
    __nv_bfloat16 hi = __float2bfloat16(v);
    __nv_bfloat16 lo = __float2bfloat16(v - __bfloat162float(hi));
    g_bimg[chunk][0][n * BSE + kk] = hi;
    g_bimg[chunk][1][n * BSE + kk] = lo;
}

// ================= fused gather + node GEMM =================
// Block: 64 nodes, 256 threads = 8 warps (2 row-groups x 4 col-groups).
// Phase 1: warp-per-node CSR mean-gather straight into SMEM as split-bf16.
// Phase 2: stage x full-width split-bf16.
// Phase 3: 4 K-chunks of 64: stage B chunk, mma.sync bf16-split (3 terms).
// IMPORTANT: xin (gather source) must NOT alias hout — gather reads arbitrary
// neighbor rows while other blocks write their outputs (ping-pong buffers).
template<int N_, bool RELU>
__global__ __launch_bounds__(256, 2)
void k_node(const float* __restrict__ xin, float* __restrict__ hout,
            const float* __restrict__ bl, const float* __restrict__ g,
            const float* __restrict__ be, const float* __restrict__ rm,
            const float* __restrict__ rv)
{
    extern __shared__ char smem[];
    constexpr int SM_A1 = 0;                     // agg hi: 64*272
    constexpr int SM_A2 = SM_A1 + 64 * AST;      // agg lo
    constexpr int SM_X1 = SM_A2 + 64 * AST;      // x hi
    constexpr int SM_X2 = SM_X1 + 64 * AST;      // x lo
    constexpr int SM_B1 = SM_X2 + 64 * AST;      // B hi chunk: N_*144
    constexpr int SM_B2 = SM_B1 + N_ * BSB;      // B lo chunk
    constexpr int SM_SC = SM_B2 + N_ * BSB;
    constexpr int SM_SH = SM_SC + 512;
    constexpr int NJ = N_ / 8 / 4;               // n8 tiles per warp (4 for N=128, 2 for N=64)

    const int tid  = threadIdx.x;
    const int wid  = tid >> 5;
    const int lane = tid & 31;
    const int wr   = (wid >> 2) * 32;            // warp row base (0 / 32)
    const int wc   = (wid & 3) * (N_ / 4);       // warp col base
    const int nb   = blockIdx.x * 64;
    const u32 sb   = smem_u32(smem);

    // ---- BN scale/shift (bias folded) ----
    if (tid < N_) {
        float s, sh;
        if (RELU) {
            float sc_ = __ldg(&g[tid]) * rsqrtf(__ldg(&rv[tid]) + 1e-5f);
            s  = sc_;
            sh = (__ldg(&bl[tid]) - __ldg(&rm[tid])) * sc_ + __ldg(&be[tid]);
        } else {
            s  = 1.0f;
            sh = __ldg(&bl[tid]);
        }
        *(float*)(smem + SM_SC + tid * 4) = s;
        *(float*)(smem + SM_SH + tid * 4) = sh;
    }

    // ---- phase 1: CSR mean-gather, warp per node, 8 nodes per warp ----
    #pragma unroll
    for (int i = 0; i < 8; i++) {
        int r = wid * 8 + i;
        int n = nb + r;
        int b = 0, e = 0;
        if (n < NN) { b = __ldg(&g_rowstart[n]); e = __ldg(&g_rowstart[n + 1]); }
        float4 a0 = make_float4(0.f, 0.f, 0.f, 0.f);
        float4 a1 = a0, a2 = a0, a3 = a0;
        int j = b;
        for (; j + 3 < e; j += 4) {
            int s0 = __ldg(&g_csrc[j]);
            int s1 = __ldg(&g_csrc[j + 1]);
            int s2 = __ldg(&g_csrc[j + 2]);
            int s3 = __ldg(&g_csrc[j + 3]);
            float4 v0 = __ldg((const float4*)(xin + (size_t)s0 * HD) + lane);
            float4 v1 = __ldg((const float4*)(xin + (size_t)s1 * HD) + lane);
            float4 v2 = __ldg((const float4*)(xin + (size_t)s2 * HD) + lane);
            float4 v3 = __ldg((const float4*)(xin + (size_t)s3 * HD) + lane);
            a0.x += v0.x; a0.y += v0.y; a0.z += v0.z; a0.w += v0.w;
            a1.x += v1.x; a1.y += v1.y; a1.z += v1.z; a1.w += v1.w;
            a2.x += v2.x; a2.y += v2.y; a2.z += v2.z; a2.w += v2.w;
            a3.x += v3.x; a3.y += v3.y; a3.z += v3.z; a3.w += v3.w;
        }
        for (; j < e; j++) {
            int s0 = __ldg(&g_csrc[j]);
            float4 v0 = __ldg((const float4*)(xin + (size_t)s0 * HD) + lane);
            a0.x += v0.x; a0.y += v0.y; a0.z += v0.z; a0.w += v0.w;
        }
        float inv = 1.0f / fmaxf((float)(e - b), 1.0f);
        float4 v;
        v.x = (a0.x + a1.x + a2.x + a3.x) * inv;
        v.y = (a0.y + a1.y + a2.y + a3.y) * inv;
        v.z = (a0.z + a1.z + a2.z + a3.z) * inv;
        v.w = (a0.w + a1.w + a2.w + a3.w) * inv;
        u64 hi, lo;
        split4(v, hi, lo);
        *(u64*)(smem + SM_A1 + r * AST + lane * 8) = hi;
        *(u64*)(smem + SM_A2 + r * AST + lane * 8) = lo;
    }

    // ---- phase 2: stage x full-width ----
    for (int idx = tid; idx < 64 * 32; idx += 256) {
        int r = idx >> 5, c4 = idx & 31;
        int n = nb + r;
        float4 v = make_float4(0.f, 0.f, 0.f, 0.f);
        if (n < NN) v = __ldg((const float4*)(xin + (size_t)n * HD) + c4);
        u64 hi, lo;
        split4(v, hi, lo);
        *(u64*)(smem + SM_X1 + r * AST + c4 * 8) = hi;
        *(u64*)(smem + SM_X2 + r * AST + c4 * 8) = lo;
    }

    // ldmatrix lane offsets (within an A buffer / B buffer)
    const u32 aOff = (u32)((wr + (lane & 15)) * AST + (lane >> 4) * 16);
    const u32 bOff = (u32)((wc + (lane & 7)) * BSB + ((lane >> 3) & 1) * 16);
    const u32 bad1 = sb + SM_B1 + bOff;
    const u32 bad2 = sb + SM_B2 + bOff;

    float acc[2][NJ][4];
    #pragma unroll
    for (int m = 0; m < 2; m++)
        #pragma unroll
        for (int j = 0; j < NJ; j++) {
            acc[m][j][0] = 0.f; acc[m][j][1] = 0.f;
            acc[m][j][2] = 0.f; acc[m][j][3] = 0.f;
        }

    // ---- phase 3: 4 K-chunks ----
    #pragma unroll
    for (int chunk = 0; chunk < 4; chunk++) {
        // stage B chunk (pre-packed padded images, raw copy)
        {
            const float4* b1s = (const float4*)&g_bimg[chunk][0][0];
            const float4* b2s = (const float4*)&g_bimg[chunk][1][0];
            for (int i = tid; i < N_ * BSB / 16; i += 256) {
                ((float4*)(smem + SM_B1))[i] = __ldg(b1s + i);
                ((float4*)(smem + SM_B2))[i] = __ldg(b2s + i);
            }
        }
        __syncthreads();   // B staged; A/X staged (first iter) / prev MMA done

        const u32 abase1 = sb + (chunk < 2 ? SM_A1 : SM_X1) + (chunk & 1) * 128 + aOff;
        const u32 abase2 = sb + (chunk < 2 ? SM_A2 : SM_X2) + (chunk & 1) * 128 + aOff;

        #pragma unroll
        for (int k16 = 0; k16 < 4; k16++) {
            u32 ah0[4], ah1[4], al0[4], al1[4];
            ldsm4(ah0, abase1 + k16 * 32);
            ldsm4(ah1, abase1 + 16 * AST + k16 * 32);
            ldsm4(al0, abase2 + k16 * 32);
            ldsm4(al1, abase2 + 16 * AST + k16 * 32);
            #pragma unroll
            for (int j = 0; j < NJ; j++) {
                u32 bh[2], blo[2];
                ldsm2(bh,  bad1 + j * 8 * BSB + k16 * 32);
                mma16816(acc[0][j], ah0, bh);
                mma16816(acc[1][j], ah1, bh);
                mma16816(acc[0][j], al0, bh);
                mma16816(acc[1][j], al1, bh);
                ldsm2(blo, bad2 + j * 8 * BSB + k16 * 32);
                mma16816(acc[0][j], ah0, blo);
                mma16816(acc[1][j], ah1, blo);
            }
        }
        __syncthreads();   // finished reading B before restage
    }

    // ---- epilogue: BN/bias/ReLU, float2 stores ----
    const int cb = (lane & 3) * 2;
    #pragma unroll
    for (int m = 0; m < 2; m++) {
        int n0 = nb + wr + m * 16 + (lane >> 2);
        int n1 = n0 + 8;
        #pragma unroll
        for (int j = 0; j < NJ; j++) {
            int c = wc + j * 8 + cb;
            float s0 = *(const float*)(smem + SM_SC + c * 4);
            float s1 = *(const float*)(smem + SM_SC + (c + 1) * 4);
            float h0 = *(const float*)(smem + SM_SH + c * 4);
            float h1 = *(const float*)(smem + SM_SH + (c + 1) * 4);
            if (n0 < NN) {
                float2 o;
                o.x = acc[m][j][0] * s0 + h0;
                o.y = acc[m][j][1] * s1 + h1;
                if (RELU) { o.x = fmaxf(o.x, 0.f); o.y = fmaxf(o.y, 0.f); }
                *(float2*)(hout + (size_t)n0 * N_ + c) = o;
            }
            if (n1 < NN) {
                float2 o;
                o.x = acc[m][j][2] * s0 + h0;
                o.y = acc[m][j][3] * s1 + h1;
                if (RELU) { o.x = fmaxf(o.x, 0.f); o.y = fmaxf(o.y, 0.f); }
                *(float2*)(hout + (size_t)n1 * N_ + c) = o;
            }
        }
    }
}

// ================= launch =================
extern "C" void kernel_launch(void* const* d_in, const int* in_sizes, int n_in,
                              void* d_out, int out_size) {
    const float* x    = (const float*)d_in[0];
    const int*   ei   = (const int*)  d_in[1];
    const float* Wl1  = (const float*)d_in[2];
    const float* bl1  = (const float*)d_in[3];
    const float* Wr1  = (const float*)d_in[4];
    const float* g1   = (const float*)d_in[5];
    const float* be1  = (const float*)d_in[6];
    const float* rm1  = (const float*)d_in[7];
    const float* rv1  = (const float*)d_in[8];
    const float* Wl2  = (const float*)d_in[9];
    const float* bl2  = (const float*)d_in[10];
    const float* Wr2  = (const float*)d_in[11];
    const float* g2   = (const float*)d_in[12];
    const float* be2  = (const float*)d_in[13];
    const float* rm2  = (const float*)d_in[14];
    const float* rv2  = (const float*)d_in[15];
    const float* Wl3  = (const float*)d_in[16];
    const float* bl3  = (const float*)d_in[17];
    const float* Wr3  = (const float*)d_in[18];
    const int* src = ei;
    const int* dst = ei + EE;
    float* out = (float*)d_out;

    float *hA, *hB;
    cudaGetSymbolAddress((void**)&hA, g_hA);
    cudaGetSymbolAddress((void**)&hB, g_hB);

    constexpr int SMEM12 = 64 * AST * 4 + HD  * BSB * 2 + 1024;   // 107520
    constexpr int SMEM3  = 64 * AST * 4 + OD3 * BSB * 2 + 1024;   // 89088
    cudaFuncSetAttribute(k_node<HD, true>,   cudaFuncAttributeMaxDynamicSharedMemorySize, SMEM12);
    cudaFuncSetAttribute(k_node<OD3, false>, cudaFuncAttributeMaxDynamicSharedMemorySize, SMEM3);

    const int EB = (EE + 255) / 256;
    const int NB = (NN + 63) / 64;   // 1563

    // CSR build (g_cnt is zero at rest; k_scan re-zeroes it after use)
    k_hist<<<EB, 256>>>(dst);                                   // #0
    k_scan<<<1, 1024>>>();                                      // #1
    k_slot<<<EB, 256>>>(src, dst);                              // #2

    // layer 1  (k_node lands in the profiled launch slot #4)
    k_bpack<HD><<<(4 * 64 * HD + 255) / 256, 256>>>(Wl1, Wr1);  // #3
    k_node<HD, true><<<NB, 256, SMEM12>>>(x, hA, bl1, g1, be1, rm1, rv1);   // #4

    // layer 2 (ping-pong: read hA, write hB — gather reads arbitrary rows)
    k_bpack<HD><<<(4 * 64 * HD + 255) / 256, 256>>>(Wl2, Wr2);
    k_node<HD, true><<<NB, 256, SMEM12>>>(hA, hB, bl2, g2, be2, rm2, rv2);

    // layer 3
    k_bpack<OD3><<<(4 * 64 * OD3 + 255) / 256, 256>>>(Wl3, Wr3);
    k_node<OD3, false><<<NB, 256, SMEM3>>>(hB, out, bl3, bl3, bl3, bl3, bl3);
}

// round 8
// speedup vs baseline: 1.2299x; 1.2299x over previous
#include <cuda_runtime.h>
#include <cuda_fp16.h>

#define NN 100000
#define EE 600000
#define HD 128
#define OD3 64
#define KSB 144          // row stride bytes for 64 fp16 cols (+8 elem pad)
#define BSE 72           // same in elements

typedef unsigned long long u64;
typedef unsigned int u32;

// ---------------- scratch (device globals) ----------------
__device__ float g_agg[(size_t)NN * HD];
__device__ float g_h[(size_t)NN * HD];
__device__ int   g_cnt[NN];          // zero at rest; re-zeroed by k_scan each call
__device__ int   g_rowstart[NN + 1];
__device__ int   g_cursor[NN];
__device__ int   g_csrc[EE];
// fp16 weight images: [layer][chunk 0..3][split hi/lo][n*BSE + kk]; B = W^T.
// chunks 0,1 = Wl k[0:64),[64:128); chunks 2,3 = Wr.
__device__ __align__(16) __half g_bimg[3][4][2][HD * BSE];

// ---------------- PTX helpers ----------------
__device__ __forceinline__ u32 smem_u32(const void* p) {
    u32 a;
    asm("{ .reg .u64 t; cvta.to.shared.u64 t, %1; cvt.u32.u64 %0, t; }" : "=r"(a) : "l"(p));
    return a;
}
__device__ __forceinline__ void ldsm4(u32* r, u32 addr) {
    asm volatile("ldmatrix.sync.aligned.m8n8.x4.shared.b16 {%0,%1,%2,%3}, [%4];"
                 : "=r"(r[0]), "=r"(r[1]), "=r"(r[2]), "=r"(r[3]) : "r"(addr));
}
__device__ __forceinline__ void ldsm2(u32* r, u32 addr) {
    asm volatile("ldmatrix.sync.aligned.m8n8.x2.shared.b16 {%0,%1}, [%2];"
                 : "=r"(r[0]), "=r"(r[1]) : "r"(addr));
}
__device__ __forceinline__ void mma16816(float* c, const u32* a, const u32* b) {
    asm volatile("mma.sync.aligned.m16n8k16.row.col.f32.f16.f16.f32 "
                 "{%0,%1,%2,%3}, {%4,%5,%6,%7}, {%8,%9}, {%0,%1,%2,%3};"
                 : "+f"(c[0]), "+f"(c[1]), "+f"(c[2]), "+f"(c[3])
                 : "r"(a[0]), "r"(a[1]), "r"(a[2]), "r"(a[3]), "r"(b[0]), "r"(b[1]));
}

// ================= CSR build =================
__global__ void k_hist(const int* __restrict__ dst) {
    int e = blockIdx.x * blockDim.x + threadIdx.x;
    if (e < EE) atomicAdd(&g_cnt[dst[e]], 1);
}

__global__ void k_scan() {   // single block, 1024 threads; restores g_cnt=0
    __shared__ int sh[1024];
    const int tid = threadIdx.x;
    const int CH = (NN + 1023) / 1024;
    int base = tid * CH;
    int end  = min(base + CH, NN);
    int s = 0;
    for (int i = base; i < end; i++) s += g_cnt[i];
    sh[tid] = s;
    __syncthreads();
    for (int off = 1; off < 1024; off <<= 1) {
        int v = (tid >= off) ? sh[tid - off] : 0;
        __syncthreads();
        sh[tid] += v;
        __syncthreads();
    }
    int run = sh[tid] - s;
    for (int i = base; i < end; i++) {
        int c = g_cnt[i];
        g_rowstart[i] = run;
        g_cursor[i]   = run;
        g_cnt[i]      = 0;
        run += c;
    }
    if (tid == 0) g_rowstart[NN] = EE;
}

__global__ void k_slot(const int* __restrict__ src, const int* __restrict__ dst) {
    int e = blockIdx.x * blockDim.x + threadIdx.x;
    if (e < EE) {
        int d = dst[e];
        int slot = atomicAdd(&g_cursor[d], 1);
        g_csrc[slot] = src[e];
    }
}

// ================= mean aggregation: warp per node =================
__global__ void k_gather(const float* __restrict__ xin) {
    int w = (blockIdx.x * blockDim.x + threadIdx.x) >> 5;
    if (w >= NN) return;
    int lane = threadIdx.x & 31;
    int b = g_rowstart[w], e2 = g_rowstart[w + 1];
    float4 a0 = make_float4(0.f, 0.f, 0.f, 0.f);
    float4 a1 = make_float4(0.f, 0.f, 0.f, 0.f);
    int j = b;
    for (; j + 1 < e2; j += 2) {
        int s0 = __ldg(&g_csrc[j]);
        int s1 = __ldg(&g_csrc[j + 1]);
        float4 v0 = __ldg((const float4*)(xin + (size_t)s0 * HD) + lane);
        float4 v1 = __ldg((const float4*)(xin + (size_t)s1 * HD) + lane);
        a0.x += v0.x; a0.y += v0.y; a0.z += v0.z; a0.w += v0.w;
        a1.x += v1.x; a1.y += v1.y; a1.z += v1.z; a1.w += v1.w;
    }
    if (j < e2) {
        int s0 = __ldg(&g_csrc[j]);
        float4 v0 = __ldg((const float4*)(xin + (size_t)s0 * HD) + lane);
        a0.x += v0.x; a0.y += v0.y; a0.z += v0.z; a0.w += v0.w;
    }
    float inv = 1.0f / fmaxf((float)(e2 - b), 1.0f);
    float4 r;
    r.x = (a0.x + a1.x) * inv; r.y = (a0.y + a1.y) * inv;
    r.z = (a0.z + a1.z) * inv; r.w = (a0.w + a1.w) * inv;
    ((float4*)(g_agg + (size_t)w * HD))[lane] = r;
}

// ================= weight prepack (all 3 layers, one launch) =================
// B[n][k] = W[k][n]; fp16 split hi/lo per element.
__global__ void k_bpackall(const float* __restrict__ Wl1, const float* __restrict__ Wr1,
                           const float* __restrict__ Wl2, const float* __restrict__ Wr2,
                           const float* __restrict__ Wl3, const float* __restrict__ Wr3) {
    int t = blockIdx.x * blockDim.x + threadIdx.x;
    if (t >= 3 * 4 * 64 * HD) return;
    int layer = t / (4 * 64 * HD);
    int rem   = t % (4 * 64 * HD);
    int chunk = rem / (64 * HD);
    int rem2  = rem % (64 * HD);
    int kk = rem2 / HD, n = rem2 % HD;
    int N_ = (layer == 2) ? OD3 : HD;
    if (n >= N_) return;
    const float* W;
    if (layer == 0)      W = (chunk < 2) ? Wl1 : Wr1;
    else if (layer == 1) W = (chunk < 2) ? Wl2 : Wr2;
    else                 W = (chunk < 2) ? Wl3 : Wr3;
    int gk = (chunk & 1) * 64 + kk;
    float v = __ldg(W + gk * N_ + n);
    __half hi = __float2half_rn(v);
    __half lo = __float2half_rn(v - __half2float(hi));
    g_bimg[layer][chunk][0][n * BSE + kk] = hi;
    g_bimg[layer][chunk][1][n * BSE + kk] = lo;
}

// ================= fused node GEMM: fp16 A, split-fp16 B, 2 MMAs/tile =================
// Block: 128 nodes, 256 threads = 8 warps (4 row-groups x 2 col-groups);
// warp tile 32 rows x N_/2 cols. K = 256 as 4 chunks of 64 (agg,agg,x,x).
// D = A*Bhi + A*Blo (exact B reconstruction; error only from fp16(A), ~2^-12).
template<int N_, bool RELU>
__global__ __launch_bounds__(256, 2)
void k_node(const float* __restrict__ xin, float* __restrict__ hout, int layer,
            const float* __restrict__ bl, const float* __restrict__ g,
            const float* __restrict__ be, const float* __restrict__ rm,
            const float* __restrict__ rv)
{
    extern __shared__ char smem[];
    constexpr int SM_A  = 0;                     // 128*144 = 18432 (fp16, 64 cols)
    constexpr int SM_B1 = SM_A + 128 * KSB;      // B hi chunk: N_*144
    constexpr int SM_B2 = SM_B1 + N_ * KSB;      // B lo chunk
    constexpr int SM_SC = SM_B2 + N_ * KSB;
    constexpr int SM_SH = SM_SC + 512;
    constexpr int NJ = N_ / 16;                  // n8 tiles per warp (8 for N=128, 4 for N=64)

    const int tid  = threadIdx.x;
    const int wid  = tid >> 5;
    const int lane = tid & 31;
    const int wr   = (wid >> 1) * 32;            // warp row base (0,32,64,96)
    const int wc   = (wid & 1) * (N_ / 2);       // warp col base
    const int nb   = blockIdx.x * 128;
    const u32 sb   = smem_u32(smem);

    // BN scale/shift (bias folded)
    if (tid < N_) {
        float s, sh;
        if (RELU) {
            float sc_ = __ldg(&g[tid]) * rsqrtf(__ldg(&rv[tid]) + 1e-5f);
            s  = sc_;
            sh = (__ldg(&bl[tid]) - __ldg(&rm[tid])) * sc_ + __ldg(&be[tid]);
        } else {
            s  = 1.0f;
            sh = __ldg(&bl[tid]);
        }
        *(float*)(smem + SM_SC + tid * 4) = s;
        *(float*)(smem + SM_SH + tid * 4) = sh;
    }

    // ldmatrix lane addresses
    const u32 aad  = sb + SM_A + (u32)((wr + (lane & 15)) * KSB + (lane >> 4) * 16);
    const u32 bOff = (u32)((wc + (lane & 7)) * KSB + ((lane >> 3) & 1) * 16);
    const u32 bad1 = sb + SM_B1 + bOff;
    const u32 bad2 = sb + SM_B2 + bOff;

    float acc[2][NJ][4];
    #pragma unroll
    for (int m = 0; m < 2; m++)
        #pragma unroll
        for (int j = 0; j < NJ; j++) {
            acc[m][j][0] = 0.f; acc[m][j][1] = 0.f;
            acc[m][j][2] = 0.f; acc[m][j][3] = 0.f;
        }

    #pragma unroll
    for (int chunk = 0; chunk < 4; chunk++) {
        // ---- stage A: 128 rows x 64 cols fp32 -> fp16 ----
        const float* asrc = (chunk < 2) ? g_agg : xin;
        const int colofs = (chunk & 1) * 16;     // float4 units
        for (int idx = tid; idx < 128 * 16; idx += 256) {
            int r = idx >> 4, c4 = idx & 15;
            int n = nb + r;
            float4 v = make_float4(0.f, 0.f, 0.f, 0.f);
            if (n < NN) v = __ldg((const float4*)(asrc + (size_t)n * HD) + colofs + c4);
            __half2 h0 = __floats2half2_rn(v.x, v.y);
            __half2 h1 = __floats2half2_rn(v.z, v.w);
            u64 p = (u64)(*(u32*)&h0) | ((u64)(*(u32*)&h1) << 32);
            *(u64*)(smem + SM_A + r * KSB + c4 * 8) = p;
        }
        // ---- stage B chunk (pre-packed padded images, raw copy) ----
        {
            const float4* b1s = (const float4*)&g_bimg[layer][chunk][0][0];
            const float4* b2s = (const float4*)&g_bimg[layer][chunk][1][0];
            for (int i = tid; i < N_ * KSB / 16; i += 256) {
                ((float4*)(smem + SM_B1))[i] = __ldg(b1s + i);
                ((float4*)(smem + SM_B2))[i] = __ldg(b2s + i);
            }
        }
        __syncthreads();

        // ---- MMA: 4 k16 steps, 2 MMAs per (m,j) tile ----
        #pragma unroll
        for (int k16 = 0; k16 < 4; k16++) {
            u32 a0[4], a1[4];
            ldsm4(a0, aad + k16 * 32);
            ldsm4(a1, aad + 16 * KSB + k16 * 32);
            #pragma unroll
            for (int j = 0; j < NJ; j++) {
                u32 bh[2], blo[2];
                ldsm2(bh,  bad1 + j * 8 * KSB + k16 * 32);
                mma16816(acc[0][j], a0, bh);
                mma16816(acc[1][j], a1, bh);
                ldsm2(blo, bad2 + j * 8 * KSB + k16 * 32);
                mma16816(acc[0][j], a0, blo);
                mma16816(acc[1][j], a1, blo);
            }
        }
        __syncthreads();   // finished reading before restage
    }

    // ---- epilogue: BN/bias/ReLU, float2 stores ----
    const int cb = (lane & 3) * 2;
    #pragma unroll
    for (int m = 0; m < 2; m++) {
        int n0 = nb + wr + m * 16 + (lane >> 2);
        int n1 = n0 + 8;
        #pragma unroll
        for (int j = 0; j < NJ; j++) {
            int c = wc + j * 8 + cb;
            float s0 = *(const float*)(smem + SM_SC + c * 4);
            float s1 = *(const float*)(smem + SM_SC + (c + 1) * 4);
            float h0 = *(const float*)(smem + SM_SH + c * 4);
            float h1 = *(const float*)(smem + SM_SH + (c + 1) * 4);
            if (n0 < NN) {
                float2 o;
                o.x = acc[m][j][0] * s0 + h0;
                o.y = acc[m][j][1] * s1 + h1;
                if (RELU) { o.x = fmaxf(o.x, 0.f); o.y = fmaxf(o.y, 0.f); }
                *(float2*)(hout + (size_t)n0 * N_ + c) = o;
            }
            if (n1 < NN) {
                float2 o;
                o.x = acc[m][j][2] * s0 + h0;
                o.y = acc[m][j][3] * s1 + h1;
                if (RELU) { o.x = fmaxf(o.x, 0.f); o.y = fmaxf(o.y, 0.f); }
                *(float2*)(hout + (size_t)n1 * N_ + c) = o;
            }
        }
    }
}

// ================= launch =================
extern "C" void kernel_launch(void* const* d_in, const int* in_sizes, int n_in,
                              void* d_out, int out_size) {
    const float* x    = (const float*)d_in[0];
    const int*   ei   = (const int*)  d_in[1];
    const float* Wl1  = (const float*)d_in[2];
    const float* bl1  = (const float*)d_in[3];
    const float* Wr1  = (const float*)d_in[4];
    const float* g1   = (const float*)d_in[5];
    const float* be1  = (const float*)d_in[6];
    const float* rm1  = (const float*)d_in[7];
    const float* rv1  = (const float*)d_in[8];
    const float* Wl2  = (const float*)d_in[9];
    const float* bl2  = (const float*)d_in[10];
    const float* Wr2  = (const float*)d_in[11];
    const float* g2   = (const float*)d_in[12];
    const float* be2  = (const float*)d_in[13];
    const float* rm2  = (const float*)d_in[14];
    const float* rv2  = (const float*)d_in[15];
    const float* Wl3  = (const float*)d_in[16];
    const float* bl3  = (const float*)d_in[17];
    const float* Wr3  = (const float*)d_in[18];
    const int* src = ei;
    const int* dst = ei + EE;
    float* out = (float*)d_out;

    float* h_p;
    cudaGetSymbolAddress((void**)&h_p, g_h);

    constexpr int SMEM12 = 128 * KSB + HD  * KSB * 2 + 1024;   // 56320
    constexpr int SMEM3  = 128 * KSB + OD3 * KSB * 2 + 1024;   // 37888
    cudaFuncSetAttribute(k_node<HD, true>,   cudaFuncAttributeMaxDynamicSharedMemorySize, SMEM12);
    cudaFuncSetAttribute(k_node<OD3, false>, cudaFuncAttributeMaxDynamicSharedMemorySize, SMEM3);

    const int EB = (EE + 255) / 256;
    const int GB = (NN * 32 + 255) / 256;
    const int NB = (NN + 127) / 128;   // 782

    // CSR build (g_cnt zero at rest; k_scan re-zeroes after use) + weight pack
    k_hist<<<EB, 256>>>(dst);                                       // #0
    k_scan<<<1, 1024>>>();                                          // #1
    k_slot<<<EB, 256>>>(src, dst);                                  // #2
    k_bpackall<<<(3 * 4 * 64 * HD + 255) / 256, 256>>>(Wl1, Wr1, Wl2, Wr2, Wl3, Wr3); // #3

    // layer 1
    k_gather<<<GB, 256>>>(x);
    k_node<HD, true><<<NB, 256, SMEM12>>>(x, h_p, 0, bl1, g1, be1, rm1, rv1);

    // layer 2 (in place safe: node reads only its own rows of g_h / g_agg)
    k_gather<<<GB, 256>>>(h_p);
    k_node<HD, true><<<NB, 256, SMEM12>>>(h_p, h_p, 1, bl2, g2, be2, rm2, rv2);

    // layer 3
    k_gather<<<GB, 256>>>(h_p);
    k_node<OD3, false><<<NB, 256, SMEM3>>>(h_p, out, 2, bl3, bl3, bl3, bl3, bl3);
}

// round 9
// speedup vs baseline: 1.3189x; 1.0723x over previous
#include <cuda_runtime.h>
#include <cuda_fp16.h>

#define NN 100000
#define EE 600000
#define HD 128
#define OD3 64
#define KSB 144          // row stride bytes for 64 fp16 cols (+8 elem pad)
#define BSE 72           // same in elements

typedef unsigned long long u64;
typedef unsigned int u32;

// ---------------- scratch (device globals) ----------------
__device__ float g_agg[(size_t)NN * HD];
__device__ float g_h[(size_t)NN * HD];
__device__ int   g_cnt[NN];          // zero at rest; re-zeroed by k_scan each call
__device__ int   g_rowstart[NN + 1];
__device__ int   g_cursor[NN];
__device__ int   g_csrc[EE];
// fp16 weight images: [layer][chunk 0..3][hi image | lo image], each image N_*BSE,
// hi+lo CONTIGUOUS per chunk (single cp.async run). B = W^T.
// chunks 0,1 = Wl k[0:64),[64:128); chunks 2,3 = Wr.
__device__ __align__(16) __half g_bimg[3][4][2 * HD * BSE];

// ---------------- PTX helpers ----------------
__device__ __forceinline__ u32 smem_u32(const void* p) {
    u32 a;
    asm("{ .reg .u64 t; cvta.to.shared.u64 t, %1; cvt.u32.u64 %0, t; }" : "=r"(a) : "l"(p));
    return a;
}
__device__ __forceinline__ void ldsm4(u32* r, u32 addr) {
    asm volatile("ldmatrix.sync.aligned.m8n8.x4.shared.b16 {%0,%1,%2,%3}, [%4];"
                 : "=r"(r[0]), "=r"(r[1]), "=r"(r[2]), "=r"(r[3]) : "r"(addr));
}
__device__ __forceinline__ void ldsm2(u32* r, u32 addr) {
    asm volatile("ldmatrix.sync.aligned.m8n8.x2.shared.b16 {%0,%1}, [%2];"
                 : "=r"(r[0]), "=r"(r[1]) : "r"(addr));
}
__device__ __forceinline__ void mma16816(float* c, const u32* a, const u32* b) {
    asm volatile("mma.sync.aligned.m16n8k16.row.col.f32.f16.f16.f32 "
                 "{%0,%1,%2,%3}, {%4,%5,%6,%7}, {%8,%9}, {%0,%1,%2,%3};"
                 : "+f"(c[0]), "+f"(c[1]), "+f"(c[2]), "+f"(c[3])
                 : "r"(a[0]), "r"(a[1]), "r"(a[2]), "r"(a[3]), "r"(b[0]), "r"(b[1]));
}
__device__ __forceinline__ void cpasync16(u32 smem_addr, const void* gptr) {
    asm volatile("cp.async.cg.shared.global [%0], [%1], 16;"
                 :: "r"(smem_addr), "l"(gptr) : "memory");
}
#define CP_COMMIT() asm volatile("cp.async.commit_group;" ::: "memory")
#define CP_WAIT0()  asm volatile("cp.async.wait_group 0;" ::: "memory")

// ================= CSR build =================
__global__ void k_hist(const int* __restrict__ dst) {
    int e = blockIdx.x * blockDim.x + threadIdx.x;
    if (e < EE) atomicAdd(&g_cnt[dst[e]], 1);
}

__global__ void k_scan() {   // single block, 1024 threads; restores g_cnt=0
    __shared__ int sh[1024];
    const int tid = threadIdx.x;
    const int CH = (NN + 1023) / 1024;
    int base = tid * CH;
    int end  = min(base + CH, NN);
    int s = 0;
    for (int i = base; i < end; i++) s += g_cnt[i];
    sh[tid] = s;
    __syncthreads();
    for (int off = 1; off < 1024; off <<= 1) {
        int v = (tid >= off) ? sh[tid - off] : 0;
        __syncthreads();
        sh[tid] += v;
        __syncthreads();
    }
    int run = sh[tid] - s;
    for (int i = base; i < end; i++) {
        int c = g_cnt[i];
        g_rowstart[i] = run;
        g_cursor[i]   = run;
        g_cnt[i]      = 0;
        run += c;
    }
    if (tid == 0) g_rowstart[NN] = EE;
}

__global__ void k_slot(const int* __restrict__ src, const int* __restrict__ dst) {
    int e = blockIdx.x * blockDim.x + threadIdx.x;
    if (e < EE) {
        int d = dst[e];
        int slot = atomicAdd(&g_cursor[d], 1);
        g_csrc[slot] = src[e];
    }
}

// ================= mean aggregation: warp per node =================
__global__ void k_gather(const float* __restrict__ xin) {
    int w = (blockIdx.x * blockDim.x + threadIdx.x) >> 5;
    if (w >= NN) return;
    int lane = threadIdx.x & 31;
    int b = g_rowstart[w], e2 = g_rowstart[w + 1];
    float4 a0 = make_float4(0.f, 0.f, 0.f, 0.f);
    float4 a1 = make_float4(0.f, 0.f, 0.f, 0.f);
    int j = b;
    for (; j + 1 < e2; j += 2) {
        int s0 = __ldg(&g_csrc[j]);
        int s1 = __ldg(&g_csrc[j + 1]);
        float4 v0 = __ldg((const float4*)(xin + (size_t)s0 * HD) + lane);
        float4 v1 = __ldg((const float4*)(xin + (size_t)s1 * HD) + lane);
        a0.x += v0.x; a0.y += v0.y; a0.z += v0.z; a0.w += v0.w;
        a1.x += v1.x; a1.y += v1.y; a1.z += v1.z; a1.w += v1.w;
    }
    if (j < e2) {
        int s0 = __ldg(&g_csrc[j]);
        float4 v0 = __ldg((const float4*)(xin + (size_t)s0 * HD) + lane);
        a0.x += v0.x; a0.y += v0.y; a0.z += v0.z; a0.w += v0.w;
    }
    float inv = 1.0f / fmaxf((float)(e2 - b), 1.0f);
    float4 r;
    r.x = (a0.x + a1.x) * inv; r.y = (a0.y + a1.y) * inv;
    r.z = (a0.z + a1.z) * inv; r.w = (a0.w + a1.w) * inv;
    ((float4*)(g_agg + (size_t)w * HD))[lane] = r;
}

// ================= weight prepack (all 3 layers, one launch) =================
// B[n][k] = W[k][n]; fp16 split: hi image then lo image, contiguous per chunk.
__global__ void k_bpackall(const float* __restrict__ Wl1, const float* __restrict__ Wr1,
                           const float* __restrict__ Wl2, const float* __restrict__ Wr2,
                           const float* __restrict__ Wl3, const float* __restrict__ Wr3) {
    int t = blockIdx.x * blockDim.x + threadIdx.x;
    if (t >= 3 * 4 * 64 * HD) return;
    int layer = t / (4 * 64 * HD);
    int rem   = t % (4 * 64 * HD);
    int chunk = rem / (64 * HD);
    int rem2  = rem % (64 * HD);
    int kk = rem2 / HD, n = rem2 % HD;
    int N_ = (layer == 2) ? OD3 : HD;
    if (n >= N_) return;
    const float* W;
    if (layer == 0)      W = (chunk < 2) ? Wl1 : Wr1;
    else if (layer == 1) W = (chunk < 2) ? Wl2 : Wr2;
    else                 W = (chunk < 2) ? Wl3 : Wr3;
    int gk = (chunk & 1) * 64 + kk;
    float v = __ldg(W + gk * N_ + n);
    __half hi = __float2half_rn(v);
    __half lo = __float2half_rn(v - __half2float(hi));
    __half* dstp = &g_bimg[layer][chunk][0];
    dstp[n * BSE + kk]            = hi;
    dstp[N_ * BSE + n * BSE + kk] = lo;   // lo image directly after hi image
}

// ================= pipelined node GEMM: fp16 A, split-fp16 B =================
// Block: 128 nodes, 256 threads = 8 warps (4 row x 2 col groups), warp tile 32 x N_/2.
// K = 256 as 4 chunks of 64 (agg,agg,x,x). D = A*Bhi + A*Blo.
// Pipeline: B(c+1) via cp.async double-buffer; A(c+1) prefetched to registers
// before MMA(c), converted+stored after. Staging latency hides under MMA.
template<int N_, bool RELU>
__global__ __launch_bounds__(256, 2)
void k_node(const float* __restrict__ xin, float* __restrict__ hout, int layer,
            const float* __restrict__ bl, const float* __restrict__ g,
            const float* __restrict__ be, const float* __restrict__ rm,
            const float* __restrict__ rv)
{
    extern __shared__ char smem[];
    constexpr int ABYT = 128 * KSB;          // one A buffer (fp16, 64 cols)
    constexpr int BBYT = N_ * KSB * 2;       // one B buffer (hi+lo)
    constexpr int SM_A0 = 0;
    constexpr int SM_B0 = 2 * ABYT;
    constexpr int SM_SC = 2 * ABYT + 2 * BBYT;
    constexpr int SM_SH = SM_SC + 512;
    constexpr int NJ = N_ / 16;              // n8 tiles per warp

    const int tid  = threadIdx.x;
    const int wid  = tid >> 5;
    const int lane = tid & 31;
    const int wr   = (wid >> 1) * 32;
    const int wc   = (wid & 1) * (N_ / 2);
    const int nb   = blockIdx.x * 128;
    const u32 sb   = smem_u32(smem);

    // BN scale/shift (bias folded)
    if (tid < N_) {
        float s, sh;
        if (RELU) {
            float sc_ = __ldg(&g[tid]) * rsqrtf(__ldg(&rv[tid]) + 1e-5f);
            s  = sc_;
            sh = (__ldg(&bl[tid]) - __ldg(&rm[tid])) * sc_ + __ldg(&be[tid]);
        } else {
            s  = 1.0f;
            sh = __ldg(&bl[tid]);
        }
        *(float*)(smem + SM_SC + tid * 4) = s;
        *(float*)(smem + SM_SH + tid * 4) = sh;
    }

    const float* srcs[4] = { g_agg, g_agg, xin, xin };
    constexpr int NB16 = BBYT / 16;          // cp.async per B buffer

    // ---- prologue: cp.async B(0), stage A(0) directly ----
    {
        const char* bsrc = (const char*)&g_bimg[layer][0][0];
        for (int i = tid; i < NB16; i += 256)
            cpasync16(sb + SM_B0 + i * 16, bsrc + i * 16);
        CP_COMMIT();
        for (int idx = tid; idx < 128 * 16; idx += 256) {
            int r = idx >> 4, c4 = idx & 15;
            int n = nb + r;
            float4 v = make_float4(0.f, 0.f, 0.f, 0.f);
            if (n < NN) v = __ldg((const float4*)(g_agg + (size_t)n * HD) + c4);
            __half2 h0 = __floats2half2_rn(v.x, v.y);
            __half2 h1 = __floats2half2_rn(v.z, v.w);
            u64 p = (u64)(*(u32*)&h0) | ((u64)(*(u32*)&h1) << 32);
            *(u64*)(smem + SM_A0 + r * KSB + c4 * 8) = p;
        }
        CP_WAIT0();
    }
    __syncthreads();

    // ldmatrix lane offsets
    const u32 aOff = (u32)((wr + (lane & 15)) * KSB + (lane >> 4) * 16);
    const u32 bOff = (u32)((wc + (lane & 7)) * KSB + ((lane >> 3) & 1) * 16);

    float acc[2][NJ][4];
    #pragma unroll
    for (int m = 0; m < 2; m++)
        #pragma unroll
        for (int j = 0; j < NJ; j++) {
            acc[m][j][0] = 0.f; acc[m][j][1] = 0.f;
            acc[m][j][2] = 0.f; acc[m][j][3] = 0.f;
        }

    const int r_pre = tid >> 4;              // row this thread stages (8 apart)
    const int c4pre = tid & 15;

    #pragma unroll
    for (int chunk = 0; chunk < 4; chunk++) {
        float4 pre[8];
        if (chunk < 3) {
            // B(c+1) -> alternate buffer (its previous contents synced-consumed)
            const char* bsrc = (const char*)&g_bimg[layer][chunk + 1][0];
            const u32 bdst = sb + SM_B0 + ((chunk + 1) & 1) * BBYT;
            for (int i = tid; i < NB16; i += 256)
                cpasync16(bdst + i * 16, bsrc + i * 16);
            CP_COMMIT();
            // A(c+1) -> registers (LDGs drain during MMA below)
            const float* s = srcs[chunk + 1];
            const int co = ((chunk + 1) & 1) * 16;
            #pragma unroll
            for (int i = 0; i < 8; i++) {
                int n = nb + r_pre + i * 16;
                pre[i] = (n < NN)
                    ? __ldg((const float4*)(s + (size_t)n * HD) + co + c4pre)
                    : make_float4(0.f, 0.f, 0.f, 0.f);
            }
        }

        // ---- MMA on chunk c ----
        const u32 abuf = sb + (chunk & 1) * ABYT + aOff;
        const u32 bad1 = sb + SM_B0 + (chunk & 1) * BBYT + bOff;
        const u32 bad2 = bad1 + N_ * KSB;
        #pragma unroll
        for (int k16 = 0; k16 < 4; k16++) {
            u32 a0[4], a1[4];
            ldsm4(a0, abuf + k16 * 32);
            ldsm4(a1, abuf + 16 * KSB + k16 * 32);
            #pragma unroll
            for (int j = 0; j < NJ; j++) {
                u32 bh[2], blo[2];
                ldsm2(bh,  bad1 + j * 8 * KSB + k16 * 32);
                mma16816(acc[0][j], a0, bh);
                mma16816(acc[1][j], a1, bh);
                ldsm2(blo, bad2 + j * 8 * KSB + k16 * 32);
                mma16816(acc[0][j], a0, blo);
                mma16816(acc[1][j], a1, blo);
            }
        }

        if (chunk < 3) {
            // convert prefetched A(c+1) into alternate A buffer
            const u32 adst = sb + ((chunk + 1) & 1) * ABYT;
            #pragma unroll
            for (int i = 0; i < 8; i++) {
                __half2 h0 = __floats2half2_rn(pre[i].x, pre[i].y);
                __half2 h1 = __floats2half2_rn(pre[i].z, pre[i].w);
                u64 p = (u64)(*(u32*)&h0) | ((u64)(*(u32*)&h1) << 32);
                *(u64*)(smem + (((chunk + 1) & 1) ? ABYT : 0)
                        + (r_pre + i * 16) * KSB + c4pre * 8) = p;
                (void)adst;
            }
            CP_WAIT0();   // B(c+1) landed
        }
        __syncthreads();  // everyone done reading c / writing c+1
    }

    // ---- epilogue: BN/bias/ReLU, float2 stores ----
    const int cb = (lane & 3) * 2;
    #pragma unroll
    for (int m = 0; m < 2; m++) {
        int n0 = nb + wr + m * 16 + (lane >> 2);
        int n1 = n0 + 8;
        #pragma unroll
        for (int j = 0; j < NJ; j++) {
            int c = wc + j * 8 + cb;
            float s0 = *(const float*)(smem + SM_SC + c * 4);
            float s1 = *(const float*)(smem + SM_SC + (c + 1) * 4);
            float h0 = *(const float*)(smem + SM_SH + c * 4);
            float h1 = *(const float*)(smem + SM_SH + (c + 1) * 4);
            if (n0 < NN) {
                float2 o;
                o.x = acc[m][j][0] * s0 + h0;
                o.y = acc[m][j][1] * s1 + h1;
                if (RELU) { o.x = fmaxf(o.x, 0.f); o.y = fmaxf(o.y, 0.f); }
                *(float2*)(hout + (size_t)n0 * N_ + c) = o;
            }
            if (n1 < NN) {
                float2 o;
                o.x = acc[m][j][2] * s0 + h0;
                o.y = acc[m][j][3] * s1 + h1;
                if (RELU) { o.x = fmaxf(o.x, 0.f); o.y = fmaxf(o.y, 0.f); }
                *(float2*)(hout + (size_t)n1 * N_ + c) = o;
            }
        }
    }
}

// ================= launch =================
extern "C" void kernel_launch(void* const* d_in, const int* in_sizes, int n_in,
                              void* d_out, int out_size) {
    const float* x    = (const float*)d_in[0];
    const int*   ei   = (const int*)  d_in[1];
    const float* Wl1  = (const float*)d_in[2];
    const float* bl1  = (const float*)d_in[3];
    const float* Wr1  = (const float*)d_in[4];
    const float* g1   = (const float*)d_in[5];
    const float* be1  = (const float*)d_in[6];
    const float* rm1  = (const float*)d_in[7];
    const float* rv1  = (const float*)d_in[8];
    const float* Wl2  = (const float*)d_in[9];
    const float* bl2  = (const float*)d_in[10];
    const float* Wr2  = (const float*)d_in[11];
    const float* g2   = (const float*)d_in[12];
    const float* be2  = (const float*)d_in[13];
    const float* rm2  = (const float*)d_in[14];
    const float* rv2  = (const float*)d_in[15];
    const float* Wl3  = (const float*)d_in[16];
    const float* bl3  = (const float*)d_in[17];
    const float* Wr3  = (const float*)d_in[18];
    const int* src = ei;
    const int* dst = ei + EE;
    float* out = (float*)d_out;

    float* h_p;
    cudaGetSymbolAddress((void**)&h_p, g_h);

    constexpr int SMEM12 = 2 * 128 * KSB + 2 * HD  * KSB * 2 + 1024;   // 111616
    constexpr int SMEM3  = 2 * 128 * KSB + 2 * OD3 * KSB * 2 + 1024;   // 74752
    cudaFuncSetAttribute(k_node<HD, true>,   cudaFuncAttributeMaxDynamicSharedMemorySize, SMEM12);
    cudaFuncSetAttribute(k_node<OD3, false>, cudaFuncAttributeMaxDynamicSharedMemorySize, SMEM3);

    const int EB = (EE + 255) / 256;
    const int GB = (NN * 32 + 255) / 256;
    const int NB = (NN + 127) / 128;   // 782

    // CSR build (g_cnt zero at rest; k_scan re-zeroes after use) + weight pack
    k_hist<<<EB, 256>>>(dst);
    k_scan<<<1, 1024>>>();
    k_slot<<<EB, 256>>>(src, dst);
    k_bpackall<<<(3 * 4 * 64 * HD + 255) / 256, 256>>>(Wl1, Wr1, Wl2, Wr2, Wl3, Wr3);

    // layer 1
    k_gather<<<GB, 256>>>(x);
    k_node<HD, true><<<NB, 256, SMEM12>>>(x, h_p, 0, bl1, g1, be1, rm1, rv1);

    // layer 2 (in place safe: node reads only its own rows of g_h / g_agg)
    k_gather<<<GB, 256>>>(h_p);
    k_node<HD, true><<<NB, 256, SMEM12>>>(h_p, h_p, 1, bl2, g2, be2, rm2, rv2);

    // layer 3
    k_gather<<<GB, 256>>>(h_p);
    k_node<OD3, false><<<NB, 256, SMEM3>>>(h_p, out, 2, bl3, bl3, bl3, bl3, bl3);
}

// round 10
// speedup vs baseline: 1.6610x; 1.2594x over previous
#include <cuda_runtime.h>
#include <cuda_fp16.h>

#define NN 100000
#define NP (NN + 128)    // padded rows so node-kernel cp.async never reads OOB
#define EE 600000
#define HD 128
#define OD3 64
#define KSB 144          // SMEM row stride bytes for 64 fp16 cols (+8 elem pad)
#define BSE 72           // same in elements

typedef unsigned long long u64;
typedef unsigned int u32;

// ---------------- scratch (device globals) ----------------
__device__ __align__(16) __half g_xh[(size_t)NP * HD];    // fp16 copy of x
__device__ __align__(16) __half g_agg[(size_t)NP * HD];   // fp16 mean-agg
__device__ __align__(16) __half g_h[(size_t)NP * HD];     // fp16 hidden acts
__device__ int   g_cnt[NN];          // zero at rest; re-zeroed by k_scan
__device__ int   g_rowstart[NN + 1];
__device__ int   g_cursor[NN];
__device__ int   g_csrc[EE];
// fp16 weight images: [layer][chunk 0..3][n*BSE + kk]; B = W^T.
// chunks 0,1 = Wl k[0:64),[64:128); chunks 2,3 = Wr.
__device__ __align__(16) __half g_bimg[3][4][HD * BSE];

// ---------------- PTX helpers ----------------
__device__ __forceinline__ u32 smem_u32(const void* p) {
    u32 a;
    asm("{ .reg .u64 t; cvta.to.shared.u64 t, %1; cvt.u32.u64 %0, t; }" : "=r"(a) : "l"(p));
    return a;
}
__device__ __forceinline__ void ldsm4(u32* r, u32 addr) {
    asm volatile("ldmatrix.sync.aligned.m8n8.x4.shared.b16 {%0,%1,%2,%3}, [%4];"
                 : "=r"(r[0]), "=r"(r[1]), "=r"(r[2]), "=r"(r[3]) : "r"(addr));
}
__device__ __forceinline__ void ldsm2(u32* r, u32 addr) {
    asm volatile("ldmatrix.sync.aligned.m8n8.x2.shared.b16 {%0,%1}, [%2];"
                 : "=r"(r[0]), "=r"(r[1]) : "r"(addr));
}
__device__ __forceinline__ void mma16816(float* c, const u32* a, const u32* b) {
    asm volatile("mma.sync.aligned.m16n8k16.row.col.f32.f16.f16.f32 "
                 "{%0,%1,%2,%3}, {%4,%5,%6,%7}, {%8,%9}, {%0,%1,%2,%3};"
                 : "+f"(c[0]), "+f"(c[1]), "+f"(c[2]), "+f"(c[3])
                 : "r"(a[0]), "r"(a[1]), "r"(a[2]), "r"(a[3]), "r"(b[0]), "r"(b[1]));
}
__device__ __forceinline__ void cpasync16(u32 smem_addr, const void* gptr) {
    asm volatile("cp.async.cg.shared.global [%0], [%1], 16;"
                 :: "r"(smem_addr), "l"(gptr) : "memory");
}
#define CP_COMMIT() asm volatile("cp.async.commit_group;" ::: "memory")

// ================= CSR build =================
__global__ void k_hist(const int* __restrict__ dst) {
    int e = blockIdx.x * blockDim.x + threadIdx.x;
    if (e < EE) atomicAdd(&g_cnt[dst[e]], 1);
}

__global__ void k_scan() {   // single block, 1024 threads; restores g_cnt=0
    __shared__ int sh[1024];
    const int tid = threadIdx.x;
    const int CH = (NN + 1023) / 1024;
    int base = tid * CH;
    int end  = min(base + CH, NN);
    int s = 0;
    for (int i = base; i < end; i++) s += g_cnt[i];
    sh[tid] = s;
    __syncthreads();
    for (int off = 1; off < 1024; off <<= 1) {
        int v = (tid >= off) ? sh[tid - off] : 0;
        __syncthreads();
        sh[tid] += v;
        __syncthreads();
    }
    int run = sh[tid] - s;
    for (int i = base; i < end; i++) {
        int c = g_cnt[i];
        g_rowstart[i] = run;
        g_cursor[i]   = run;
        g_cnt[i]      = 0;
        run += c;
    }
    if (tid == 0) g_rowstart[NN] = EE;
}

__global__ void k_slot(const int* __restrict__ src, const int* __restrict__ dst) {
    int e = blockIdx.x * blockDim.x + threadIdx.x;
    if (e < EE) {
        int d = dst[e];
        int slot = atomicAdd(&g_cursor[d], 1);
        g_csrc[slot] = src[e];
    }
}

// ================= x -> fp16 copy =================
__global__ void k_xhalf(const float* __restrict__ x) {
    int t = blockIdx.x * blockDim.x + threadIdx.x;
    if (t >= NN * HD / 8) return;
    float4 v0 = __ldg((const float4*)x + t * 2);
    float4 v1 = __ldg((const float4*)x + t * 2 + 1);
    __half2 h0 = __floats2half2_rn(v0.x, v0.y);
    __half2 h1 = __floats2half2_rn(v0.z, v0.w);
    __half2 h2 = __floats2half2_rn(v1.x, v1.y);
    __half2 h3 = __floats2half2_rn(v1.z, v1.w);
    uint4 p;
    p.x = *(u32*)&h0; p.y = *(u32*)&h1; p.z = *(u32*)&h2; p.w = *(u32*)&h3;
    ((uint4*)g_xh)[t] = p;
}

// ================= mean aggregation: warp per node, fp16 rows =================
// Row = 256B; lane loads uint2 (4 halves). Accumulate fp32, write fp16 agg.
__global__ void k_gather(const __half* __restrict__ xin) {
    int w = (blockIdx.x * blockDim.x + threadIdx.x) >> 5;
    if (w >= NN) return;
    int lane = threadIdx.x & 31;
    int b = g_rowstart[w], e2 = g_rowstart[w + 1];
    float a0 = 0.f, a1 = 0.f, a2 = 0.f, a3 = 0.f;
    float b0 = 0.f, b1 = 0.f, b2 = 0.f, b3 = 0.f;
    int j = b;
    for (; j + 1 < e2; j += 2) {
        int s0 = __ldg(&g_csrc[j]);
        int s1 = __ldg(&g_csrc[j + 1]);
        uint2 p0 = __ldg((const uint2*)(xin + (size_t)s0 * HD) + lane);
        uint2 p1 = __ldg((const uint2*)(xin + (size_t)s1 * HD) + lane);
        float2 f0 = __half22float2(*(__half2*)&p0.x);
        float2 f1 = __half22float2(*(__half2*)&p0.y);
        float2 g0 = __half22float2(*(__half2*)&p1.x);
        float2 g1 = __half22float2(*(__half2*)&p1.y);
        a0 += f0.x; a1 += f0.y; a2 += f1.x; a3 += f1.y;
        b0 += g0.x; b1 += g0.y; b2 += g1.x; b3 += g1.y;
    }
    if (j < e2) {
        int s0 = __ldg(&g_csrc[j]);
        uint2 p0 = __ldg((const uint2*)(xin + (size_t)s0 * HD) + lane);
        float2 f0 = __half22float2(*(__half2*)&p0.x);
        float2 f1 = __half22float2(*(__half2*)&p0.y);
        a0 += f0.x; a1 += f0.y; a2 += f1.x; a3 += f1.y;
    }
    float inv = 1.0f / fmaxf((float)(e2 - b), 1.0f);
    __half2 o0 = __floats2half2_rn((a0 + b0) * inv, (a1 + b1) * inv);
    __half2 o1 = __floats2half2_rn((a2 + b2) * inv, (a3 + b3) * inv);
    uint2 o;
    o.x = *(u32*)&o0; o.y = *(u32*)&o1;
    ((uint2*)(g_agg + (size_t)w * HD))[lane] = o;
}

// ================= weight prepack (all 3 layers, one launch) =================
// B[n][k] = W[k][n]; single fp16 image per chunk.
__global__ void k_bpackall(const float* __restrict__ Wl1, const float* __restrict__ Wr1,
                           const float* __restrict__ Wl2, const float* __restrict__ Wr2,
                           const float* __restrict__ Wl3, const float* __restrict__ Wr3) {
    int t = blockIdx.x * blockDim.x + threadIdx.x;
    if (t >= 3 * 4 * 64 * HD) return;
    int layer = t / (4 * 64 * HD);
    int rem   = t % (4 * 64 * HD);
    int chunk = rem / (64 * HD);
    int rem2  = rem % (64 * HD);
    int kk = rem2 / HD, n = rem2 % HD;
    int N_ = (layer == 2) ? OD3 : HD;
    if (n >= N_) return;
    const float* W;
    if (layer == 0)      W = (chunk < 2) ? Wl1 : Wr1;
    else if (layer == 1) W = (chunk < 2) ? Wl2 : Wr2;
    else                 W = (chunk < 2) ? Wl3 : Wr3;
    int gk = (chunk & 1) * 64 + kk;
    g_bimg[layer][chunk][n * BSE + kk] = __float2half_rn(__ldg(W + gk * N_ + n));
}

// ================= pipelined node GEMM: fp16 A and B, cp.async everything =====
// Block: 128 nodes, 256 threads = 8 warps (4 row x 2 col groups), warp tile 32 x N_/2.
// K = 256 as 4 chunks of 64 (agg,agg,x,x). Both A and B double-buffered cp.async.
// LAST=false: fp16 out (g_h) with BN+ReLU; LAST=true: fp32 out, bias only.
template<int N_, bool LAST>
__global__ __launch_bounds__(256, 2)
void k_node(const __half* __restrict__ xh, void* __restrict__ hout, int layer,
            const float* __restrict__ bl, const float* __restrict__ g,
            const float* __restrict__ be, const float* __restrict__ rm,
            const float* __restrict__ rv)
{
    extern __shared__ char smem[];
    constexpr int ABYT = 128 * KSB;          // one A buffer
    constexpr int BBYT = N_ * KSB;           // one B buffer
    constexpr int SM_B0 = 2 * ABYT;
    constexpr int SM_SC = 2 * ABYT + 2 * BBYT;
    constexpr int SM_SH = SM_SC + 512;
    constexpr int NJ = N_ / 16;

    const int tid  = threadIdx.x;
    const int wid  = tid >> 5;
    const int lane = tid & 31;
    const int wr   = (wid >> 1) * 32;
    const int wc   = (wid & 1) * (N_ / 2);
    const int nb   = blockIdx.x * 128;
    const u32 sb   = smem_u32(smem);

    // BN scale/shift (bias folded)
    if (tid < N_) {
        float s, sh;
        if (!LAST) {
            float sc_ = __ldg(&g[tid]) * rsqrtf(__ldg(&rv[tid]) + 1e-5f);
            s  = sc_;
            sh = (__ldg(&bl[tid]) - __ldg(&rm[tid])) * sc_ + __ldg(&be[tid]);
        } else {
            s  = 1.0f;
            sh = __ldg(&bl[tid]);
        }
        *(float*)(smem + SM_SC + tid * 4) = s;
        *(float*)(smem + SM_SH + tid * 4) = sh;
    }

    // ---- async stage of one chunk (A: 1024 x 16B, B: BBYT/16 x 16B) ----
    auto stage = [&](int cc, int buf) {
        const __half* asrc = (cc < 2) ? g_agg : xh;
        const int co = (cc & 1) * 128;       // byte offset within 256B row
        const u32 adst = sb + buf * ABYT;
        for (int idx = tid; idx < 1024; idx += 256) {
            int r = idx >> 3, i = idx & 7;
            cpasync16(adst + r * KSB + i * 16,
                      (const char*)(asrc + (size_t)(nb + r) * HD) + co + i * 16);
        }
        const char* bsrc = (const char*)&g_bimg[layer][cc][0];
        const u32 bdst = sb + SM_B0 + buf * BBYT;
        for (int i = tid; i < BBYT / 16; i += 256)
            cpasync16(bdst + i * 16, bsrc + i * 16);
    };

    stage(0, 0);
    CP_COMMIT();

    const u32 aOff = (u32)((wr + (lane & 15)) * KSB + (lane >> 4) * 16);
    const u32 bOff = (u32)((wc + (lane & 7)) * KSB + ((lane >> 3) & 1) * 16);

    float acc[2][NJ][4];
    #pragma unroll
    for (int m = 0; m < 2; m++)
        #pragma unroll
        for (int j = 0; j < NJ; j++) {
            acc[m][j][0] = 0.f; acc[m][j][1] = 0.f;
            acc[m][j][2] = 0.f; acc[m][j][3] = 0.f;
        }

    #pragma unroll
    for (int chunk = 0; chunk < 4; chunk++) {
        if (chunk < 3) {
            stage(chunk + 1, (chunk + 1) & 1);
            CP_COMMIT();
            asm volatile("cp.async.wait_group 1;" ::: "memory");
        } else {
            asm volatile("cp.async.wait_group 0;" ::: "memory");
        }
        __syncthreads();   // chunk's buffers visible to all threads

        const u32 abuf = sb + (chunk & 1) * ABYT + aOff;
        const u32 bbuf = sb + SM_B0 + (chunk & 1) * BBYT + bOff;
        #pragma unroll
        for (int k16 = 0; k16 < 4; k16++) {
            u32 a0[4], a1[4];
            ldsm4(a0, abuf + k16 * 32);
            ldsm4(a1, abuf + 16 * KSB + k16 * 32);
            #pragma unroll
            for (int j = 0; j < NJ; j++) {
                u32 bh[2];
                ldsm2(bh, bbuf + j * 8 * KSB + k16 * 32);
                mma16816(acc[0][j], a0, bh);
                mma16816(acc[1][j], a1, bh);
            }
        }
        __syncthreads();   // done reading before next-next stage overwrites
    }

    // ---- epilogue ----
    const int cb = (lane & 3) * 2;
    #pragma unroll
    for (int m = 0; m < 2; m++) {
        int n0 = nb + wr + m * 16 + (lane >> 2);
        int n1 = n0 + 8;
        #pragma unroll
        for (int j = 0; j < NJ; j++) {
            int c = wc + j * 8 + cb;
            float s0 = *(const float*)(smem + SM_SC + c * 4);
            float s1 = *(const float*)(smem + SM_SC + (c + 1) * 4);
            float h0 = *(const float*)(smem + SM_SH + c * 4);
            float h1 = *(const float*)(smem + SM_SH + (c + 1) * 4);
            float ox0 = acc[0 + 0][j][0]; // placeholder avoid unused warn
            (void)ox0;
            #pragma unroll
            for (int hh = 0; hh < 2; hh++) {
                int n = (hh == 0) ? n0 : n1;
                if (n >= NN) continue;
                float vx = acc[m][j][hh * 2 + 0] * s0 + h0;
                float vy = acc[m][j][hh * 2 + 1] * s1 + h1;
                if (!LAST) {
                    vx = fmaxf(vx, 0.f);
                    vy = fmaxf(vy, 0.f);
                    __half2 hv = __floats2half2_rn(vx, vy);
                    *(u32*)((__half*)hout + (size_t)n * N_ + c) = *(u32*)&hv;
                } else {
                    float2 o; o.x = vx; o.y = vy;
                    *(float2*)((float*)hout + (size_t)n * N_ + c) = o;
                }
            }
        }
    }
}

// ================= launch =================
extern "C" void kernel_launch(void* const* d_in, const int* in_sizes, int n_in,
                              void* d_out, int out_size) {
    const float* x    = (const float*)d_in[0];
    const int*   ei   = (const int*)  d_in[1];
    const float* Wl1  = (const float*)d_in[2];
    const float* bl1  = (const float*)d_in[3];
    const float* Wr1  = (const float*)d_in[4];
    const float* g1   = (const float*)d_in[5];
    const float* be1  = (const float*)d_in[6];
    const float* rm1  = (const float*)d_in[7];
    const float* rv1  = (const float*)d_in[8];
    const float* Wl2  = (const float*)d_in[9];
    const float* bl2  = (const float*)d_in[10];
    const float* Wr2  = (const float*)d_in[11];
    const float* g2   = (const float*)d_in[12];
    const float* be2  = (const float*)d_in[13];
    const float* rm2  = (const float*)d_in[14];
    const float* rv2  = (const float*)d_in[15];
    const float* Wl3  = (const float*)d_in[16];
    const float* bl3  = (const float*)d_in[17];
    const float* Wr3  = (const float*)d_in[18];
    const int* src = ei;
    const int* dst = ei + EE;
    float* out = (float*)d_out;

    __half *xh_p, *h_p;
    cudaGetSymbolAddress((void**)&xh_p, g_xh);
    cudaGetSymbolAddress((void**)&h_p,  g_h);

    constexpr int SMEM12 = 2 * 128 * KSB + 2 * HD  * KSB + 1024;   // 74752
    constexpr int SMEM3  = 2 * 128 * KSB + 2 * OD3 * KSB + 1024;   // 56320
    cudaFuncSetAttribute(k_node<HD, false>, cudaFuncAttributeMaxDynamicSharedMemorySize, SMEM12);
    cudaFuncSetAttribute(k_node<OD3, true>, cudaFuncAttributeMaxDynamicSharedMemorySize, SMEM3);

    const int EB = (EE + 255) / 256;
    const int GB = (NN * 32 + 255) / 256;
    const int NB = (NN + 127) / 128;   // 782

    // CSR build + fp16 conversions + weight pack
    k_hist<<<EB, 256>>>(dst);
    k_scan<<<1, 1024>>>();
    k_slot<<<EB, 256>>>(src, dst);
    k_xhalf<<<(NN * HD / 8 + 255) / 256, 256>>>(x);
    k_bpackall<<<(3 * 4 * 64 * HD + 255) / 256, 256>>>(Wl1, Wr1, Wl2, Wr2, Wl3, Wr3);

    // layer 1
    k_gather<<<GB, 256>>>(xh_p);
    k_node<HD, false><<<NB, 256, SMEM12>>>(xh_p, h_p, 0, bl1, g1, be1, rm1, rv1);

    // layer 2 (in place safe: node reads only its own rows of g_h / g_agg)
    k_gather<<<GB, 256>>>(h_p);
    k_node<HD, false><<<NB, 256, SMEM12>>>(h_p, h_p, 1, bl2, g2, be2, rm2, rv2);

    // layer 3
    k_gather<<<GB, 256>>>(h_p);
    k_node<OD3, true><<<NB, 256, SMEM3>>>(h_p, out, 2, bl3, bl3, bl3, bl3, bl3);
}